// round 1
// baseline (speedup 1.0000x reference)
#include <cuda_runtime.h>
#include <math.h>

#define BB 4
#define TT 2048
#define HH 768
#define NHH 12
#define DHH 64
#define KQQ 1024
#define KKVV 1024

// Scratch (allocation-free rule: __device__ globals)
__device__ __align__(16) float g_Q[(size_t)BB * KQQ * HH];
__device__ __align__(16) float g_K[(size_t)BB * KKVV * HH];
__device__ __align__(16) float g_V[(size_t)BB * KKVV * HH];
__device__ __align__(16) float g_vmean[BB * HH];

// ---------------------------------------------------------------------------
// Kernel 1: gathered QKV projection.  y[b,k,o] = sum_h x[b,idx[k],h]*W[o,h]+b[o]
// Tile 64x64, K-chunk 16, 256 threads, 4x4 per thread register blocking.
// ---------------------------------------------------------------------------
__global__ __launch_bounds__(256) void qkv_kernel(
    const float* __restrict__ hidden,
    const float* __restrict__ Wq, const float* __restrict__ bq,
    const float* __restrict__ Wk, const float* __restrict__ bk,
    const float* __restrict__ Wv, const float* __restrict__ bv,
    const int* __restrict__ qidx, const int* __restrict__ kvidx)
{
    __shared__ float As[16][68];
    __shared__ float Bs[16][68];
    __shared__ int toks[64];

    const int nt = blockIdx.x;   // 0..11  (N tiles of 64 over 768)
    const int mt = blockIdx.y;   // 0..15  (M tiles of 64 over 1024)
    const int z  = blockIdx.z;   // p*B + b
    const int p = z >> 2, b = z & 3;

    const float* W; const float* bias; const int* idx; float* outp;
    if (p == 0)      { W = Wq; bias = bq; idx = qidx;  outp = g_Q; }
    else if (p == 1) { W = Wk; bias = bk; idx = kvidx; outp = g_K; }
    else             { W = Wv; bias = bv; idx = kvidx; outp = g_V; }

    const int tid = threadIdx.x;
    const int ty = tid >> 4, tx = tid & 15;
    const int row = tid >> 2;          // 0..63
    const int c4  = (tid & 3) * 4;     // 0,4,8,12

    if (tid < 64) toks[tid] = idx[b * KQQ + mt * 64 + tid];
    __syncthreads();

    const float* arow = hidden + ((size_t)b * TT + toks[row]) * HH + c4;
    const float* brow = W + (size_t)(nt * 64 + row) * HH + c4;

    float acc[4][4] = {};
    for (int k0 = 0; k0 < HH; k0 += 16) {
        float4 av = *(const float4*)(arow + k0);
        float4 wv = *(const float4*)(brow + k0);
        __syncthreads();
        As[c4 + 0][row] = av.x; As[c4 + 1][row] = av.y;
        As[c4 + 2][row] = av.z; As[c4 + 3][row] = av.w;
        Bs[c4 + 0][row] = wv.x; Bs[c4 + 1][row] = wv.y;
        Bs[c4 + 2][row] = wv.z; Bs[c4 + 3][row] = wv.w;
        __syncthreads();
        #pragma unroll
        for (int kk = 0; kk < 16; kk++) {
            float4 a = *(const float4*)&As[kk][ty * 4];
            float4 w = *(const float4*)&Bs[kk][tx * 4];
            acc[0][0] += a.x * w.x; acc[0][1] += a.x * w.y; acc[0][2] += a.x * w.z; acc[0][3] += a.x * w.w;
            acc[1][0] += a.y * w.x; acc[1][1] += a.y * w.y; acc[1][2] += a.y * w.z; acc[1][3] += a.y * w.w;
            acc[2][0] += a.z * w.x; acc[2][1] += a.z * w.y; acc[2][2] += a.z * w.z; acc[2][3] += a.z * w.w;
            acc[3][0] += a.w * w.x; acc[3][1] += a.w * w.y; acc[3][2] += a.w * w.z; acc[3][3] += a.w * w.w;
        }
    }

    float4 bias4 = *(const float4*)(bias + nt * 64 + tx * 4);
    float* orow = outp + ((size_t)b * KQQ + mt * 64 + ty * 4) * HH + nt * 64 + tx * 4;
    #pragma unroll
    for (int ii = 0; ii < 4; ii++) {
        float4 r = make_float4(acc[ii][0] + bias4.x, acc[ii][1] + bias4.y,
                               acc[ii][2] + bias4.z, acc[ii][3] + bias4.w);
        *(float4*)(orow + (size_t)ii * HH) = r;
    }
}

// ---------------------------------------------------------------------------
// Kernel 2: per-batch mean of V rows -> g_vmean[b][768]
// ---------------------------------------------------------------------------
__global__ void vmean_kernel()
{
    const int b = blockIdx.y;
    const int d = blockIdx.x * 256 + threadIdx.x;   // 0..767
    const float* vb = g_V + (size_t)b * KKVV * HH + d;
    float s = 0.f;
    for (int r = 0; r < KKVV; r++) s += vb[(size_t)r * HH];
    g_vmean[b * HH + d] = s * (1.0f / KKVV);
}

// ---------------------------------------------------------------------------
// Kernel 3: fill whole output with vmean (non-q rows keep it; q rows get
// overwritten by the attention kernel which runs after in-stream).
// ---------------------------------------------------------------------------
__global__ void fill_kernel(float* __restrict__ out)
{
    const int i = blockIdx.x * blockDim.x + threadIdx.x;
    const int total = BB * TT * (HH / 4);
    if (i >= total) return;
    const int d4 = i % (HH / 4);
    const int b  = i / (TT * (HH / 4));
    float4 v = ((const float4*)g_vmean)[b * (HH / 4) + d4];
    ((float4*)out)[i] = v;
}

// ---------------------------------------------------------------------------
// Kernel 4: flash attention over the 1024 kv rows. One block = 64 q rows of
// one (b, h). 16x16 threads, 4x4 register tiles, online softmax.
// ---------------------------------------------------------------------------
__global__ __launch_bounds__(256) void attn_kernel(
    const int* __restrict__ qidx, float* __restrict__ out)
{
    extern __shared__ float sm[];
    float* Qs = sm;                 // [64 d][68]  (transposed: Qs[d*68+i])
    float* Ks = Qs + 64 * 68;       // [64 d][68]  (Ks[d*68+j])
    float* Vs = Ks + 64 * 68;       // [64 j][68]  (Vs[j*68+d])
    float* Ps = Vs + 64 * 68;       // [64 j][68]  (Ps[j*68+i])
    __shared__ int qtok[64];

    const int mt = blockIdx.x, h = blockIdx.y, b = blockIdx.z;
    const int tid = threadIdx.x;
    const int ty = tid >> 4, tx = tid & 15;
    const int row = tid >> 2;          // 0..63
    const int cbase = (tid & 3) * 4;   // 0,4,8,12

    if (tid < 64) qtok[tid] = qidx[b * KQQ + mt * 64 + tid];

    // Load Q tile (64x64) transposed into Qs
    const float* Qg = g_Q + ((size_t)b * KQQ + mt * 64 + row) * HH + h * DHH;
    #pragma unroll
    for (int cc = 0; cc < 4; cc++) {
        const int c = cbase + cc * 16;
        float4 qv = *(const float4*)(Qg + c);
        Qs[(c + 0) * 68 + row] = qv.x; Qs[(c + 1) * 68 + row] = qv.y;
        Qs[(c + 2) * 68 + row] = qv.z; Qs[(c + 3) * 68 + row] = qv.w;
    }
    __syncthreads();

    float m_i[4], l_i[4], o[4][4];
    #pragma unroll
    for (int ii = 0; ii < 4; ii++) {
        m_i[ii] = -INFINITY; l_i[ii] = 0.f;
        #pragma unroll
        for (int jj = 0; jj < 4; jj++) o[ii][jj] = 0.f;
    }

    const float* Kg = g_K + (size_t)b * KKVV * HH + h * DHH;
    const float* Vg = g_V + (size_t)b * KKVV * HH + h * DHH;

    for (int kt = 0; kt < KKVV / 64; kt++) {
        const float* Kt = Kg + (size_t)(kt * 64 + row) * HH;
        const float* Vt = Vg + (size_t)(kt * 64 + row) * HH;
        float4 kreg[4], vreg[4];
        #pragma unroll
        for (int cc = 0; cc < 4; cc++) kreg[cc] = *(const float4*)(Kt + cbase + cc * 16);
        #pragma unroll
        for (int cc = 0; cc < 4; cc++) vreg[cc] = *(const float4*)(Vt + cbase + cc * 16);

        // Store K transposed (its last readers finished before prev tile's 2nd bar)
        #pragma unroll
        for (int cc = 0; cc < 4; cc++) {
            const int c = cbase + cc * 16;
            Ks[(c + 0) * 68 + row] = kreg[cc].x; Ks[(c + 1) * 68 + row] = kreg[cc].y;
            Ks[(c + 2) * 68 + row] = kreg[cc].z; Ks[(c + 3) * 68 + row] = kreg[cc].w;
        }
        __syncthreads();   // A: K (and Q on first iter) visible

        float s[4][4] = {};
        #pragma unroll 8
        for (int d = 0; d < 64; d++) {
            float4 a = *(const float4*)&Qs[d * 68 + ty * 4];
            float4 k4 = *(const float4*)&Ks[d * 68 + tx * 4];
            s[0][0] += a.x * k4.x; s[0][1] += a.x * k4.y; s[0][2] += a.x * k4.z; s[0][3] += a.x * k4.w;
            s[1][0] += a.y * k4.x; s[1][1] += a.y * k4.y; s[1][2] += a.y * k4.z; s[1][3] += a.y * k4.w;
            s[2][0] += a.z * k4.x; s[2][1] += a.z * k4.y; s[2][2] += a.z * k4.z; s[2][3] += a.z * k4.w;
            s[3][0] += a.w * k4.x; s[3][1] += a.w * k4.y; s[3][2] += a.w * k4.z; s[3][3] += a.w * k4.w;
        }

        // Online softmax (rows live across the 16 tx lanes; shuffles stay in half)
        #pragma unroll
        for (int ii = 0; ii < 4; ii++) {
            #pragma unroll
            for (int jj = 0; jj < 4; jj++) s[ii][jj] *= 0.125f;   // 1/sqrt(64)
            float rm = fmaxf(fmaxf(s[ii][0], s[ii][1]), fmaxf(s[ii][2], s[ii][3]));
            #pragma unroll
            for (int mm = 1; mm < 16; mm <<= 1)
                rm = fmaxf(rm, __shfl_xor_sync(0xffffffffu, rm, mm));
            const float mn = fmaxf(m_i[ii], rm);
            const float corr = __expf(m_i[ii] - mn);
            m_i[ii] = mn;
            float rs = 0.f;
            #pragma unroll
            for (int jj = 0; jj < 4; jj++) { s[ii][jj] = __expf(s[ii][jj] - mn); rs += s[ii][jj]; }
            #pragma unroll
            for (int mm = 1; mm < 16; mm <<= 1)
                rs += __shfl_xor_sync(0xffffffffu, rs, mm);
            l_i[ii] = l_i[ii] * corr + rs;
            #pragma unroll
            for (int jj = 0; jj < 4; jj++) o[ii][jj] *= corr;
        }

        // Write P transposed; store V (prev Vs readers finished before bar A)
        #pragma unroll
        for (int ii = 0; ii < 4; ii++)
            #pragma unroll
            for (int jj = 0; jj < 4; jj++)
                Ps[(tx * 4 + jj) * 68 + ty * 4 + ii] = s[ii][jj];
        #pragma unroll
        for (int cc = 0; cc < 4; cc++)
            *(float4*)&Vs[row * 68 + cbase + cc * 16] = vreg[cc];
        __syncthreads();   // B: P and V visible

        #pragma unroll 8
        for (int j = 0; j < 64; j++) {
            float4 a = *(const float4*)&Ps[j * 68 + ty * 4];
            float4 v4 = *(const float4*)&Vs[j * 68 + tx * 4];
            o[0][0] += a.x * v4.x; o[0][1] += a.x * v4.y; o[0][2] += a.x * v4.z; o[0][3] += a.x * v4.w;
            o[1][0] += a.y * v4.x; o[1][1] += a.y * v4.y; o[1][2] += a.y * v4.z; o[1][3] += a.y * v4.w;
            o[2][0] += a.z * v4.x; o[2][1] += a.z * v4.y; o[2][2] += a.z * v4.z; o[2][3] += a.z * v4.w;
            o[3][0] += a.w * v4.x; o[3][1] += a.w * v4.y; o[3][2] += a.w * v4.z; o[3][3] += a.w * v4.w;
        }
    }

    // Epilogue: normalize and scatter to output tokens
    #pragma unroll
    for (int ii = 0; ii < 4; ii++) {
        const float inv = 1.0f / l_i[ii];
        const int tok = qtok[ty * 4 + ii];
        float4 r = make_float4(o[ii][0] * inv, o[ii][1] * inv, o[ii][2] * inv, o[ii][3] * inv);
        *(float4*)(out + ((size_t)b * TT + tok) * HH + h * DHH + tx * 4) = r;
    }
}

// ---------------------------------------------------------------------------
extern "C" void kernel_launch(void* const* d_in, const int* in_sizes, int n_in,
                              void* d_out, int out_size)
{
    const float* hidden = (const float*)d_in[0];
    // d_in[1] = attention_mask (all zeros) -- unused
    const float* Wq = (const float*)d_in[2];
    const float* bq = (const float*)d_in[3];
    const float* Wk = (const float*)d_in[4];
    const float* bk = (const float*)d_in[5];
    const float* Wv = (const float*)d_in[6];
    const float* bv = (const float*)d_in[7];
    const int* qidx  = (const int*)d_in[8];
    const int* kvidx = (const int*)d_in[9];
    float* out = (float*)d_out;

    const int attn_smem = 4 * 64 * 68 * (int)sizeof(float);   // 69632 B
    cudaFuncSetAttribute(attn_kernel, cudaFuncAttributeMaxDynamicSharedMemorySize, attn_smem);

    qkv_kernel<<<dim3(12, 16, 12), 256>>>(hidden, Wq, bq, Wk, bk, Wv, bv, qidx, kvidx);
    vmean_kernel<<<dim3(3, BB), 256>>>();
    fill_kernel<<<(BB * TT * (HH / 4) + 255) / 256, 256>>>(out);
    attn_kernel<<<dim3(16, NHH, BB), 256, attn_smem>>>(qidx, out);
}

// round 3
// speedup vs baseline: 2.7329x; 2.7329x over previous
#include <cuda_runtime.h>
#include <math.h>
#include <cstdint>

#define BB 4
#define TT 2048
#define HH 768
#define NHH 12
#define DHH 64
#define KQQ 1024
#define KKVV 1024

// Scratch (allocation-free rule: __device__ globals)
__device__ __align__(16) float g_Q[(size_t)BB * KQQ * HH];
__device__ __align__(16) float g_K[(size_t)BB * KKVV * HH];
__device__ __align__(16) float g_V[(size_t)BB * KKVV * HH];
__device__ __align__(16) float g_vpart[8][BB * HH];
__device__ __align__(16) float g_vmean[BB * HH];

// ---------------------------------------------------------------------------
// helpers
// ---------------------------------------------------------------------------
__device__ __forceinline__ float f2tf32(float x) {
    uint32_t r;
    asm("cvt.rna.tf32.f32 %0, %1;" : "=r"(r) : "f"(x));
    return __uint_as_float(r);
}
__device__ __forceinline__ float4 cvt4(float4 v) {
    v.x = f2tf32(v.x); v.y = f2tf32(v.y); v.z = f2tf32(v.z); v.w = f2tf32(v.w);
    return v;
}
// D = A(16x8,row) * B(8x8,col) + D   (tf32 in, f32 accum)
__device__ __forceinline__ void mma_tf32(float4& d,
    uint32_t a0, uint32_t a1, uint32_t a2, uint32_t a3,
    uint32_t b0, uint32_t b1)
{
    asm volatile(
        "mma.sync.aligned.m16n8k8.row.col.f32.tf32.tf32.f32 "
        "{%0,%1,%2,%3}, {%4,%5,%6,%7}, {%8,%9}, {%0,%1,%2,%3};\n"
        : "+f"(d.x), "+f"(d.y), "+f"(d.z), "+f"(d.w)
        : "r"(a0), "r"(a1), "r"(a2), "r"(a3), "r"(b0), "r"(b1));
}
__device__ __forceinline__ uint32_t fb(float x) { return __float_as_uint(x); }

// ===========================================================================
// Kernel 1: gathered QKV projection with tf32 mma.sync.
// C[128 tok][128 och] per block. 8 warps, each 64(m)x32(n). BK=32.
// grid = (6 n-tiles, 8 m-tiles, 12 = proj*4+b)
// ===========================================================================
#define QKV_STRIDE 36
__global__ __launch_bounds__(256, 2) void qkv_kernel(
    const float* __restrict__ hidden,
    const float* __restrict__ Wq, const float* __restrict__ bq,
    const float* __restrict__ Wk, const float* __restrict__ bk,
    const float* __restrict__ Wv, const float* __restrict__ bv,
    const int* __restrict__ qidx, const int* __restrict__ kvidx)
{
    __shared__ float As[128][QKV_STRIDE];
    __shared__ float Bs[128][QKV_STRIDE];
    __shared__ int toks[128];
    __shared__ float bias_s[128];

    const int nt = blockIdx.x;   // 0..5
    const int mt = blockIdx.y;   // 0..7
    const int z = blockIdx.z;
    const int p = z >> 2, b = z & 3;

    const float* W; const float* bias; const int* idx; float* outp;
    if (p == 0)      { W = Wq; bias = bq; idx = qidx;  outp = g_Q; }
    else if (p == 1) { W = Wk; bias = bk; idx = kvidx; outp = g_K; }
    else             { W = Wv; bias = bv; idx = kvidx; outp = g_V; }

    const int tid = threadIdx.x;
    const int lane = tid & 31, wid = tid >> 5;
    const int gid = lane >> 2, tig = lane & 3;
    const int wr = wid & 1, wc = wid >> 1;   // warp m(2) x n(4)

    if (tid < 128) {
        toks[tid] = idx[b * KQQ + mt * 128 + tid];
        bias_s[tid] = bias[nt * 128 + tid];
    }
    __syncthreads();

    const int row = tid >> 1, half = tid & 1;
    const float* ag = hidden + ((size_t)b * TT + toks[row]) * HH + half * 16;
    const float* bg = W + (size_t)(nt * 128 + row) * HH + half * 16;

    float4 c[4][4];
    #pragma unroll
    for (int i = 0; i < 4; i++)
        #pragma unroll
        for (int j = 0; j < 4; j++) c[i][j] = make_float4(0.f, 0.f, 0.f, 0.f);

    for (int kt = 0; kt < HH / 32; kt++) {
        float4 av[4], wv[4];
        #pragma unroll
        for (int i = 0; i < 4; i++) {
            av[i] = *(const float4*)(ag + kt * 32 + i * 4);
            wv[i] = *(const float4*)(bg + kt * 32 + i * 4);
        }
        __syncthreads();   // prev compute done
        #pragma unroll
        for (int i = 0; i < 4; i++) {
            *(float4*)&As[row][half * 16 + i * 4] = cvt4(av[i]);
            *(float4*)&Bs[row][half * 16 + i * 4] = cvt4(wv[i]);
        }
        __syncthreads();   // tiles visible

        #pragma unroll
        for (int ks = 0; ks < 32; ks += 8) {
            uint32_t a[4][4], bf[4][2];
            #pragma unroll
            for (int mtl = 0; mtl < 4; mtl++) {
                const int bm = wr * 64 + mtl * 16;
                a[mtl][0] = fb(As[bm + gid    ][ks + tig    ]);
                a[mtl][1] = fb(As[bm + gid + 8][ks + tig    ]);
                a[mtl][2] = fb(As[bm + gid    ][ks + tig + 4]);
                a[mtl][3] = fb(As[bm + gid + 8][ks + tig + 4]);
            }
            #pragma unroll
            for (int ntl = 0; ntl < 4; ntl++) {
                const int bn = wc * 32 + ntl * 8;
                bf[ntl][0] = fb(Bs[bn + gid][ks + tig    ]);
                bf[ntl][1] = fb(Bs[bn + gid][ks + tig + 4]);
            }
            #pragma unroll
            for (int mtl = 0; mtl < 4; mtl++)
                #pragma unroll
                for (int ntl = 0; ntl < 4; ntl++)
                    mma_tf32(c[mtl][ntl], a[mtl][0], a[mtl][1], a[mtl][2], a[mtl][3],
                             bf[ntl][0], bf[ntl][1]);
        }
    }

    // epilogue
    #pragma unroll
    for (int mtl = 0; mtl < 4; mtl++) {
        const int grow = mt * 128 + wr * 64 + mtl * 16 + gid;
        float* o0 = outp + ((size_t)b * KQQ + grow) * HH + nt * 128;
        float* o1 = o0 + 8 * HH;
        #pragma unroll
        for (int ntl = 0; ntl < 4; ntl++) {
            const int col = wc * 32 + ntl * 8 + 2 * tig;
            const float bx = bias_s[col], by = bias_s[col + 1];
            *(float2*)(o0 + col) = make_float2(c[mtl][ntl].x + bx, c[mtl][ntl].y + by);
            *(float2*)(o1 + col) = make_float2(c[mtl][ntl].z + bx, c[mtl][ntl].w + by);
        }
    }
}

// ---------------------------------------------------------------------------
// Kernel 2a/2b: per-batch mean of V rows (two-stage, deterministic)
// ---------------------------------------------------------------------------
__global__ void vmean_part()
{
    const int d = blockIdx.x * 256 + threadIdx.x;   // 0..767
    const int rc = blockIdx.y, b = blockIdx.z;
    const float* vb = g_V + ((size_t)b * KKVV + rc * 128) * HH + d;
    float s = 0.f;
    #pragma unroll 8
    for (int r = 0; r < 128; r++) s += vb[(size_t)r * HH];
    g_vpart[rc][b * HH + d] = s;
}
__global__ void vmean_combine()
{
    const int i = blockIdx.x * 256 + threadIdx.x;   // 0..3071
    float s = 0.f;
    #pragma unroll
    for (int p = 0; p < 8; p++) s += g_vpart[p][i];
    g_vmean[i] = s * (1.0f / KKVV);
}

// ---------------------------------------------------------------------------
// Kernel 3: fill output with vmean (non-q rows keep it)
// ---------------------------------------------------------------------------
__global__ void fill_kernel(float* __restrict__ out)
{
    const int i = blockIdx.x * blockDim.x + threadIdx.x;
    const int total = BB * TT * (HH / 4);
    if (i >= total) return;
    const int d4 = i % (HH / 4);
    const int b  = i / (TT * (HH / 4));
    float4 v = ((const float4*)g_vmean)[b * (HH / 4) + d4];
    ((float4*)out)[i] = v;
}

// ===========================================================================
// Kernel 4: flash attention on tf32 mma.sync.
// Block: 128 q rows of one (b,h). 8 warps x 16 rows. KV tiles of 64.
// smem: Ks[64][68], Vs[2][64][68], Ps[128][68] (Ps doubles as Q staging)
// ===========================================================================
#define AST 68
__global__ __launch_bounds__(256, 2) void attn_kernel(
    const int* __restrict__ qidx, float* __restrict__ out)
{
    extern __shared__ float sm[];
    float* Ks = sm;                       // [64][AST]
    float* Vs = sm + 64 * AST;            // [2][64][AST]
    float* Ps = sm + 3 * 64 * AST;        // [128][AST]
    __shared__ int qtok[128];

    const int mt = blockIdx.x, h = blockIdx.y, b = blockIdx.z;
    const int tid = threadIdx.x;
    const int lane = tid & 31, wid = tid >> 5;
    const int gid = lane >> 2, tig = lane & 3;
    const int wrow = wid * 16;

    if (tid < 128) qtok[tid] = qidx[b * KQQ + mt * 128 + tid];

    // stage Q (pre-scaled by 1/8, tf32) into Ps[128][64]
    {
        const int r = tid >> 1, hf = tid & 1;
        const float* Qg = g_Q + ((size_t)b * KQQ + mt * 128 + r) * HH + h * DHH + hf * 32;
        #pragma unroll
        for (int i = 0; i < 8; i++) {
            float4 q = *(const float4*)(Qg + i * 4);
            q.x = f2tf32(q.x * 0.125f); q.y = f2tf32(q.y * 0.125f);
            q.z = f2tf32(q.z * 0.125f); q.w = f2tf32(q.w * 0.125f);
            *(float4*)&Ps[r * AST + hf * 32 + i * 4] = q;
        }
    }
    __syncthreads();

    // Q fragments, register resident
    uint32_t qa[8][4];
    #pragma unroll
    for (int ks = 0; ks < 8; ks++) {
        qa[ks][0] = fb(Ps[(wrow + gid    ) * AST + ks * 8 + tig    ]);
        qa[ks][1] = fb(Ps[(wrow + gid + 8) * AST + ks * 8 + tig    ]);
        qa[ks][2] = fb(Ps[(wrow + gid    ) * AST + ks * 8 + tig + 4]);
        qa[ks][3] = fb(Ps[(wrow + gid + 8) * AST + ks * 8 + tig + 4]);
    }

    float4 o[8];
    #pragma unroll
    for (int i = 0; i < 8; i++) o[i] = make_float4(0.f, 0.f, 0.f, 0.f);
    float m0 = -INFINITY, m1 = -INFINITY, l0 = 0.f, l1 = 0.f;

    const int r = tid >> 2, q4 = (tid & 3) * 16;
    const float* Kg = g_K + ((size_t)b * KKVV + r) * HH + h * DHH + q4;
    const float* Vg = g_V + ((size_t)b * KKVV + r) * HH + h * DHH + q4;

    for (int kt = 0; kt < KKVV / 64; kt++) {
        float* Vb = Vs + (kt & 1) * 64 * AST;
        // load K,V tile, store to smem (K single buffer, V double buffer)
        {
            const size_t off = (size_t)kt * 64 * HH;
            #pragma unroll
            for (int i = 0; i < 4; i++) {
                float4 kv = *(const float4*)(Kg + off + i * 4);
                *(float4*)&Ks[r * AST + q4 + i * 4] = cvt4(kv);
            }
            #pragma unroll
            for (int i = 0; i < 4; i++) {
                float4 vv = *(const float4*)(Vg + off + i * 4);
                *(float4*)&Vb[r * AST + q4 + i * 4] = cvt4(vv);
            }
        }
        __syncthreads();   // A: K (+V later via B) visible; prev PV done

        // S = Q K^T  (per warp: 16 x 64)
        float4 s[8];
        #pragma unroll
        for (int i = 0; i < 8; i++) s[i] = make_float4(0.f, 0.f, 0.f, 0.f);
        #pragma unroll
        for (int ks = 0; ks < 8; ks++) {
            #pragma unroll
            for (int ntl = 0; ntl < 8; ntl++) {
                const uint32_t b0 = fb(Ks[(ntl * 8 + gid) * AST + ks * 8 + tig    ]);
                const uint32_t b1 = fb(Ks[(ntl * 8 + gid) * AST + ks * 8 + tig + 4]);
                mma_tf32(s[ntl], qa[ks][0], qa[ks][1], qa[ks][2], qa[ks][3], b0, b1);
            }
        }

        // online softmax (lane owns rows gid (x,y) and gid+8 (z,w))
        float rm0 = -INFINITY, rm1 = -INFINITY;
        #pragma unroll
        for (int i = 0; i < 8; i++) {
            rm0 = fmaxf(rm0, fmaxf(s[i].x, s[i].y));
            rm1 = fmaxf(rm1, fmaxf(s[i].z, s[i].w));
        }
        rm0 = fmaxf(rm0, __shfl_xor_sync(0xffffffffu, rm0, 1));
        rm0 = fmaxf(rm0, __shfl_xor_sync(0xffffffffu, rm0, 2));
        rm1 = fmaxf(rm1, __shfl_xor_sync(0xffffffffu, rm1, 1));
        rm1 = fmaxf(rm1, __shfl_xor_sync(0xffffffffu, rm1, 2));
        const float mn0 = fmaxf(m0, rm0), mn1 = fmaxf(m1, rm1);
        const float corr0 = __expf(m0 - mn0), corr1 = __expf(m1 - mn1);
        m0 = mn0; m1 = mn1;
        float rs0 = 0.f, rs1 = 0.f;
        #pragma unroll
        for (int i = 0; i < 8; i++) {
            s[i].x = __expf(s[i].x - mn0); s[i].y = __expf(s[i].y - mn0);
            s[i].z = __expf(s[i].z - mn1); s[i].w = __expf(s[i].w - mn1);
            rs0 += s[i].x + s[i].y;
            rs1 += s[i].z + s[i].w;
        }
        rs0 += __shfl_xor_sync(0xffffffffu, rs0, 1);
        rs0 += __shfl_xor_sync(0xffffffffu, rs0, 2);
        rs1 += __shfl_xor_sync(0xffffffffu, rs1, 1);
        rs1 += __shfl_xor_sync(0xffffffffu, rs1, 2);
        l0 = l0 * corr0 + rs0;
        l1 = l1 * corr1 + rs1;
        #pragma unroll
        for (int i = 0; i < 8; i++) {
            o[i].x *= corr0; o[i].y *= corr0;
            o[i].z *= corr1; o[i].w *= corr1;
        }

        // store P (tf32) to smem
        #pragma unroll
        for (int ntl = 0; ntl < 8; ntl++) {
            const int cbase = ntl * 8 + 2 * tig;
            *(float2*)&Ps[(wrow + gid    ) * AST + cbase] =
                make_float2(f2tf32(s[ntl].x), f2tf32(s[ntl].y));
            *(float2*)&Ps[(wrow + gid + 8) * AST + cbase] =
                make_float2(f2tf32(s[ntl].z), f2tf32(s[ntl].w));
        }
        __syncthreads();   // B: P visible (V was stored pre-A)

        // O += P V (per warp: 16 x 64)
        #pragma unroll
        for (int ks = 0; ks < 8; ks++) {
            const uint32_t pa0 = fb(Ps[(wrow + gid    ) * AST + ks * 8 + tig    ]);
            const uint32_t pa1 = fb(Ps[(wrow + gid + 8) * AST + ks * 8 + tig    ]);
            const uint32_t pa2 = fb(Ps[(wrow + gid    ) * AST + ks * 8 + tig + 4]);
            const uint32_t pa3 = fb(Ps[(wrow + gid + 8) * AST + ks * 8 + tig + 4]);
            #pragma unroll
            for (int ntl = 0; ntl < 8; ntl++) {
                const uint32_t v0 = fb(Vb[(ks * 8 + tig    ) * AST + ntl * 8 + gid]);
                const uint32_t v1 = fb(Vb[(ks * 8 + tig + 4) * AST + ntl * 8 + gid]);
                mma_tf32(o[ntl], pa0, pa1, pa2, pa3, v0, v1);
            }
        }
    }

    // epilogue: normalize and scatter
    const float inv0 = 1.0f / l0, inv1 = 1.0f / l1;
    const int tok0 = qtok[wrow + gid], tok1 = qtok[wrow + gid + 8];
    float* O0 = out + ((size_t)b * TT + tok0) * HH + h * DHH;
    float* O1 = out + ((size_t)b * TT + tok1) * HH + h * DHH;
    #pragma unroll
    for (int ntl = 0; ntl < 8; ntl++) {
        const int col = ntl * 8 + 2 * tig;
        *(float2*)(O0 + col) = make_float2(o[ntl].x * inv0, o[ntl].y * inv0);
        *(float2*)(O1 + col) = make_float2(o[ntl].z * inv1, o[ntl].w * inv1);
    }
}

// ---------------------------------------------------------------------------
extern "C" void kernel_launch(void* const* d_in, const int* in_sizes, int n_in,
                              void* d_out, int out_size)
{
    const float* hidden = (const float*)d_in[0];
    // d_in[1] = attention_mask (all zeros) -- unused
    const float* Wq = (const float*)d_in[2];
    const float* bq = (const float*)d_in[3];
    const float* Wk = (const float*)d_in[4];
    const float* bk = (const float*)d_in[5];
    const float* Wv = (const float*)d_in[6];
    const float* bv = (const float*)d_in[7];
    const int* qidx  = (const int*)d_in[8];
    const int* kvidx = (const int*)d_in[9];
    float* out = (float*)d_out;

    const int attn_smem = (64 * AST + 2 * 64 * AST + 128 * AST) * (int)sizeof(float); // 87040
    cudaFuncSetAttribute(attn_kernel, cudaFuncAttributeMaxDynamicSharedMemorySize, attn_smem);

    qkv_kernel<<<dim3(6, 8, 12), 256>>>(hidden, Wq, bq, Wk, bk, Wv, bv, qidx, kvidx);
    vmean_part<<<dim3(3, 8, 4), 256>>>();
    vmean_combine<<<12, 256>>>();
    fill_kernel<<<(BB * TT * (HH / 4) + 255) / 256, 256>>>(out);
    attn_kernel<<<dim3(8, NHH, BB), 256, attn_smem>>>(qidx, out);
}